// round 2
// baseline (speedup 1.0000x reference)
#include <cuda_runtime.h>
#include <cuda_bf16.h>

#define UDIM 9
#define VDIM 9
#define UV   81
#define MD_  4
#define WS_  3
#define HDIM 256
#define WDIM 448
#define HW   (HDIM * WDIM)     // 114688
#define QHW  (HW / 4)          // 28672 float4-pixels per (b)
#define BDIM 4
#define NQUAD (BDIM * QHW)     // 114688 threads total

#define INV_LOG49 0.25694918f
#define INV_LOG81 0.22755998f

__global__ __launch_bounds__(128) void flow_reg_kernel(
    const float* __restrict__ x, float* __restrict__ out)
{
    int t = blockIdx.x * 128 + threadIdx.x;
    if (t >= NQUAD) return;

    int b = t / QHW;
    int q = t - b * QHW;          // float4 index within (h,w) plane

    const float* base = x + (long)b * (UV * HW) + (long)q * 4;

    // ================= pass 1: max + argmax per pixel =================
    float m[4];
    int   am[4];
    {
        float4 v0 = __ldg((const float4*)base);
        m[0] = v0.x; m[1] = v0.y; m[2] = v0.z; m[3] = v0.w;
        am[0] = am[1] = am[2] = am[3] = 0;
    }
#pragma unroll
    for (int c = 1; c < UV; ++c) {
        float4 vv = __ldg((const float4*)(base + (long)c * HW));
        float a0 = vv.x, a1 = vv.y, a2 = vv.z, a3 = vv.w;
        if (a0 > m[0]) { m[0] = a0; am[0] = c; }
        if (a1 > m[1]) { m[1] = a1; am[1] = c; }
        if (a2 > m[2]) { m[2] = a2; am[2] = c; }
        if (a3 > m[3]) { m[3] = a3; am[3] = c; }
    }

    int iu[4], iv[4];
#pragma unroll
    for (int p = 0; p < 4; ++p) {
        iu[p] = am[p] / VDIM;
        iv[p] = am[p] - iu[p] * VDIM;
    }

    // ================= pass 2: fused sums (reads hit L2) =================
    float Zg[4] = {0,0,0,0}, Sg[4] = {0,0,0,0};
    float Zl[4] = {0,0,0,0}, Sl[4] = {0,0,0,0};
    float Su[4] = {0,0,0,0}, Sv[4] = {0,0,0,0};

#pragma unroll
    for (int c = 0; c < UV; ++c) {
        const int ui = c / VDIM;       // compile-time
        const int vi = c - ui * VDIM;  // compile-time
        float4 vv = __ldg((const float4*)(base + (long)c * HW));
        float arr[4] = {vv.x, vv.y, vv.z, vv.w};
#pragma unroll
        for (int p = 0; p < 4; ++p) {
            float e = __expf(arr[p] - m[p]);
            Zg[p] += e;
            Sg[p] = fmaf(e, arr[p], Sg[p]);
            // |ui - iu| <= 3 && |vi - iv| <= 3  (ui,vi compile-time)
            bool in = ((unsigned)(iu[p] - ui + WS_) <= 2u * WS_) &&
                      ((unsigned)(iv[p] - vi + WS_) <= 2u * WS_);
            if (in) {
                Zl[p] += e;
                Sl[p] = fmaf(e, arr[p], Sl[p]);
                Su[p] = fmaf(e, (float)(ui - MD_), Su[p]);
                Sv[p] = fmaf(e, (float)(vi - MD_), Sv[p]);
            }
        }
    }

    // ================= outputs =================
    float4 ox, oy, le, ge;
    float* px_ox = (float*)&ox;
    float* px_oy = (float*)&oy;
    float* px_le = (float*)&le;
    float* px_ge = (float*)&ge;
#pragma unroll
    for (int p = 0; p < 4; ++p) {
        float invZl = __frcp_rn(Zl[p]);
        float invZg = __frcp_rn(Zg[p]);
        px_ox[p] = Su[p] * invZl;
        px_oy[p] = Sv[p] * invZl;
        // entropy identity: -sum p log p = log Z + m - (sum e*x)/Z
        px_le[p] = (__logf(Zl[p]) + m[p] - Sl[p] * invZl) * INV_LOG49;
        px_ge[p] = (__logf(Zg[p]) + m[p] - Sg[p] * invZg) * INV_LOG81;
    }

    float* flow = out;
    float* ent  = out + (long)BDIM * 2 * HW;
    *(float4*)(flow + (long)(b * 2 + 0) * HW + (long)q * 4) = ox;
    *(float4*)(flow + (long)(b * 2 + 1) * HW + (long)q * 4) = oy;
    *(float4*)(ent  + (long)(b * 2 + 0) * HW + (long)q * 4) = le;
    *(float4*)(ent  + (long)(b * 2 + 1) * HW + (long)q * 4) = ge;
}

extern "C" void kernel_launch(void* const* d_in, const int* in_sizes, int n_in,
                              void* d_out, int out_size)
{
    const float* x = (const float*)d_in[0];
    float* out = (float*)d_out;
    dim3 block(128);
    dim3 grid((NQUAD + 127) / 128);   // 896 blocks
    flow_reg_kernel<<<grid, block>>>(x, out);
}

// round 3
// speedup vs baseline: 1.9865x; 1.9865x over previous
#include <cuda_runtime.h>
#include <cuda_bf16.h>

#define UDIM 9
#define VDIM 9
#define UV   81
#define MD_  4
#define WS_  3
#define HDIM 256
#define WDIM 448
#define HW   (HDIM * WDIM)     // 114688
#define BDIM 4
#define NPIX (BDIM * HW)       // 458752
#define TPB  128

#define INV_LOG49 0.25694918f
#define INV_LOG81 0.22755998f

__global__ __launch_bounds__(TPB) void flow_reg_kernel(
    const float* __restrict__ x, float* __restrict__ out)
{
    __shared__ float sbuf[UV * TPB];   // per-thread private columns, conflict-free

    int tid = threadIdx.x;
    int t   = blockIdx.x * TPB + tid;  // grid sized exactly: no bounds check needed
    int b   = t / HW;
    int pix = t - b * HW;

    const float* xp = x + (long)b * (UV * HW) + pix;

    // ---- pass 1: stream channels; stash in smem; track max+argmax ----
    float m;
    int am = 0;
    {
        float v = __ldg(xp);
        sbuf[tid] = v;
        m = v;
    }
#pragma unroll
    for (int c = 1; c < UV; ++c) {
        float v = __ldg(xp + (long)c * HW);
        sbuf[c * TPB + tid] = v;
        if (v > m) { m = v; am = c; }
    }

    int iu = am / VDIM;
    int iv = am - iu * VDIM;

    // ---- pass 2: fused sums from smem (thread-private -> no sync) ----
    float Zg = 0.f, Sg = 0.f;   // global softmax: sum e, sum e*x
    float Zl = 0.f, Sl = 0.f;   // masked
    float Su = 0.f, Sv = 0.f;   // flow numerators
#pragma unroll
    for (int c = 0; c < UV; ++c) {
        const int ui = c / VDIM;        // compile-time
        const int vi = c - ui * VDIM;   // compile-time
        float v = sbuf[c * TPB + tid];
        float e = __expf(v - m);
        Zg += e;
        Sg = fmaf(e, v, Sg);
        bool in = ((unsigned)(iu - ui + WS_) <= 2u * WS_) &&
                  ((unsigned)(iv - vi + WS_) <= 2u * WS_);
        if (in) {
            Zl += e;
            Sl = fmaf(e, v, Sl);
            Su = fmaf(e, (float)(ui - MD_), Su);
            Sv = fmaf(e, (float)(vi - MD_), Sv);
        }
    }

    // ---- outputs: entropy via  -sum p log p = log Z + m - (sum e*x)/Z ----
    float invZl = __frcp_rn(Zl);
    float invZg = __frcp_rn(Zg);
    float outx  = Su * invZl;
    float outy  = Sv * invZl;
    float lent  = (__logf(Zl) + m - Sl * invZl) * INV_LOG49;
    float gent  = (__logf(Zg) + m - Sg * invZg) * INV_LOG81;

    float* flow = out;
    float* ent  = out + (long)BDIM * 2 * HW;
    flow[(long)(b * 2 + 0) * HW + pix] = outx;
    flow[(long)(b * 2 + 1) * HW + pix] = outy;
    ent [(long)(b * 2 + 0) * HW + pix] = lent;
    ent [(long)(b * 2 + 1) * HW + pix] = gent;
}

extern "C" void kernel_launch(void* const* d_in, const int* in_sizes, int n_in,
                              void* d_out, int out_size)
{
    const float* x = (const float*)d_in[0];
    float* out = (float*)d_out;
    flow_reg_kernel<<<NPIX / TPB, TPB>>>(x, out);   // 3584 blocks x 128
}

// round 5
// speedup vs baseline: 1.9932x; 1.0034x over previous
#include <cuda_runtime.h>
#include <cuda_bf16.h>

#define UDIM 9
#define VDIM 9
#define UV   81
#define MD_  4
#define WS_  3
#define HDIM 256
#define WDIM 448
#define HW   (HDIM * WDIM)     // 114688
#define HW2  (HW / 2)          // 57344 float2 pairs per (b,plane)
#define BDIM 4
#define NPAIR (BDIM * HW2)     // 229376 threads
#define TPB  64

#define INV_LOG49 0.25694918f
#define INV_LOG81 0.22755998f
#define LOG2E     1.44269504f

typedef unsigned long long ull;

__device__ __forceinline__ ull pack2(float lo, float hi) {
    ull r;
    asm("mov.b64 %0, {%1, %2};" : "=l"(r) : "f"(lo), "f"(hi));
    return r;
}
__device__ __forceinline__ void unpack2(ull v, float& lo, float& hi) {
    asm("mov.b64 {%0, %1}, %2;" : "=f"(lo), "=f"(hi) : "l"(v));
}
__device__ __forceinline__ ull ffma2(ull a, ull b, ull c) {
    ull d;
    asm("fma.rn.f32x2 %0, %1, %2, %3;" : "=l"(d) : "l"(a), "l"(b), "l"(c));
    return d;
}
__device__ __forceinline__ ull fadd2(ull a, ull b) {
    ull d;
    asm("add.rn.f32x2 %0, %1, %2;" : "=l"(d) : "l"(a), "l"(b));
    return d;
}
__device__ __forceinline__ float ex2f(float t) {
    float r;
    asm("ex2.approx.f32 %0, %1;" : "=f"(r) : "f"(t));
    return r;
}

__global__ __launch_bounds__(TPB) void flow_reg_kernel(
    const float* __restrict__ x, float* __restrict__ out)
{
    __shared__ float2 sbuf[UV][TPB];   // 41472 B; per-thread private columns

    const int tid = threadIdx.x;
    const int t   = blockIdx.x * TPB + tid;   // pair index (exact grid)
    const int b   = t / HW2;
    const int q   = t - b * HW2;              // float2 index in (h,w) plane

    const float2* xp = (const float2*)(x + (size_t)b * (UV * HW)) + q;

    // ---- pass 1: stream channels to smem; max + argmax per pixel ----
    float m0, m1;
    int am0 = 0, am1 = 0;
    {
        float2 v = __ldg(xp);
        sbuf[0][tid] = v;
        m0 = v.x; m1 = v.y;
    }
#pragma unroll
    for (int c = 1; c < UV; ++c) {
        float2 v = __ldg(xp + (size_t)c * HW2);
        sbuf[c][tid] = v;
        if (v.x > m0) { m0 = v.x; am0 = c; }
        if (v.y > m1) { m1 = v.y; am1 = c; }
    }

    const int iu0 = am0 / VDIM, iv0 = am0 - (am0 / VDIM) * VDIM;
    const int iu1 = am1 / VDIM, iv1 = am1 - (am1 / VDIM) * VDIM;

    // 9-bit window masks: bit k set iff |k - i| <= 3
    const unsigned umask0 = (0x7Fu << iu0) >> WS_;
    const unsigned vmask0 = (0x7Fu << iv0) >> WS_;
    const unsigned umask1 = (0x7Fu << iu1) >> WS_;
    const unsigned vmask1 = (0x7Fu << iv1) >> WS_;

    const ull log2e2 = pack2(LOG2E, LOG2E);
    const ull mneg2  = pack2(-m0 * LOG2E, -m1 * LOG2E);

    // packed accumulators
    ull Zg2 = 0, Sg2 = 0, Zl2 = 0, Sl2 = 0, Su2 = 0, Sv2 = 0;

#pragma unroll
    for (int u = 0; u < UDIM; ++u) {
        const unsigned rm0 = ((umask0 >> u) & 1u) ? vmask0 : 0u;
        const unsigned rm1 = ((umask1 >> u) & 1u) ? vmask1 : 0u;
        ull rowZ = 0;
#pragma unroll
        for (int v = 0; v < VDIM; ++v) {
            const int c = u * VDIM + v;
            float2 xv = sbuf[c][tid];
            ull x2 = pack2(xv.x, xv.y);
            ull t2 = ffma2(x2, log2e2, mneg2);      // (x - m) * log2e
            float t0, t1;
            unpack2(t2, t0, t1);
            float e0 = ex2f(t0);
            float e1 = ex2f(t1);
            ull e2 = pack2(e0, e1);
            Zg2 = fadd2(Zg2, e2);
            Sg2 = ffma2(e2, x2, Sg2);
            float em0 = (rm0 & (1u << v)) ? e0 : 0.0f;
            float em1 = (rm1 & (1u << v)) ? e1 : 0.0f;
            ull em2 = pack2(em0, em1);
            rowZ = fadd2(rowZ, em2);
            Sl2  = ffma2(em2, x2, Sl2);
            const float wv = (float)(v - MD_);
            Sv2  = ffma2(em2, pack2(wv, wv), Sv2);
        }
        Zl2 = fadd2(Zl2, rowZ);
        const float wu = (float)(u - MD_);
        Su2 = ffma2(rowZ, pack2(wu, wu), Su2);
    }

    // ---- epilogue per pixel ----
    float Zg[2], Sg[2], Zl[2], Sl[2], Su[2], Sv[2], m[2];
    unpack2(Zg2, Zg[0], Zg[1]);
    unpack2(Sg2, Sg[0], Sg[1]);
    unpack2(Zl2, Zl[0], Zl[1]);
    unpack2(Sl2, Sl[0], Sl[1]);
    unpack2(Su2, Su[0], Su[1]);
    unpack2(Sv2, Sv[0], Sv[1]);
    m[0] = m0; m[1] = m1;

    float2 ox, oy, le, ge;
    float* pox = &ox.x; float* poy = &oy.x;
    float* ple = &le.x; float* pge = &ge.x;
#pragma unroll
    for (int p = 0; p < 2; ++p) {
        float invZl = __frcp_rn(Zl[p]);
        float invZg = __frcp_rn(Zg[p]);
        pox[p] = Su[p] * invZl;
        poy[p] = Sv[p] * invZl;
        // -sum p log p = log Z + m - (sum e*x)/Z
        ple[p] = (__logf(Zl[p]) + m[p] - Sl[p] * invZl) * INV_LOG49;
        pge[p] = (__logf(Zg[p]) + m[p] - Sg[p] * invZg) * INV_LOG81;
    }

    float2* flow = (float2*)out;
    float2* ent  = (float2*)(out + (size_t)BDIM * 2 * HW);
    flow[(size_t)(b * 2 + 0) * HW2 + q] = ox;
    flow[(size_t)(b * 2 + 1) * HW2 + q] = oy;
    ent [(size_t)(b * 2 + 0) * HW2 + q] = le;
    ent [(size_t)(b * 2 + 1) * HW2 + q] = ge;
}

extern "C" void kernel_launch(void* const* d_in, const int* in_sizes, int n_in,
                              void* d_out, int out_size)
{
    const float* x = (const float*)d_in[0];
    float* out = (float*)d_out;
    flow_reg_kernel<<<NPAIR / TPB, TPB>>>(x, out);   // 3584 blocks x 64
}